// round 5
// baseline (speedup 1.0000x reference)
#include <cuda_runtime.h>
#include <math.h>

// ACT collapses to a per-row scalar recursion:
//   p = sigmoid(x_row . W + b)           (scalar per row)
//   state = c * x_row,  c follows the same update with x -> 1
//   ponder = nup + rem
// Two warps per row (64 lanes, 4 float4 each): low register footprint ->
// full occupancy, while keeping MLP=4 independent LDG.128 per thread.
// All lanes redundantly run the exact fp32 scalar recursion.

#define D 1024
#define THREADS 256          // 8 warps -> 4 rows per block (2 warps/row)
#define ROWS_PER_BLOCK 4
#define MAX_STEPS 20
#define THRESHOLD 0.99f

__global__ __launch_bounds__(THREADS, 8) void act_kernel(
    const float* __restrict__ x,
    const float* __restrict__ W,
    const float* __restrict__ bvec,
    float* __restrict__ out_state,
    float* __restrict__ out_ponder,   // may be null
    int n_rows)
{
    __shared__ float warp_part[THREADS / 32];

    const int lane = threadIdx.x & 31;
    const int warp = threadIdx.x >> 5;
    const int half = warp & 1;                      // which half of the row
    const int row  = blockIdx.x * ROWS_PER_BLOCK + (warp >> 1);

    const bool active = (row < n_rows);
    const size_t base = (size_t)row * D;
    const float4* __restrict__ x4 = reinterpret_cast<const float4*>(x + base);
    const float4* __restrict__ w4 = reinterpret_cast<const float4*>(W);

    // Each lane: 4 independent LDG.128 (64 lanes x 4 x 4 floats = 1024 = D).
    // Coalesced: (i, half) selects a contiguous 32-float4 segment.
    float4 xv[4];
    float dot = 0.0f;
    if (active) {
        #pragma unroll
        for (int i = 0; i < 4; i++)
            xv[i] = x4[i * 64 + half * 32 + lane];
        #pragma unroll
        for (int i = 0; i < 4; i++) {
            const float4 wv = __ldg(&w4[i * 64 + half * 32 + lane]);
            dot += xv[i].x * wv.x + xv[i].y * wv.y
                 + xv[i].z * wv.z + xv[i].w * wv.w;
        }
    }

    // Warp-level reduce of this half-row.
    #pragma unroll
    for (int o = 16; o > 0; o >>= 1)
        dot += __shfl_xor_sync(0xffffffffu, dot, o);
    if (lane == 0) warp_part[warp] = dot;
    __syncthreads();

    if (!active) return;

    // Combine the two half-row partials (deterministic order: even + odd).
    const float z = warp_part[warp & ~1] + warp_part[warp | 1] + bvec[0];
    const float p = 1.0f / (1.0f + expf(-z));

    // Exact replication of the reference scan in scalar fp32 (all lanes).
    float hp = 0.0f, rem = 0.0f, nup = 0.0f, c = 0.0f;
    #pragma unroll
    for (int s = 0; s < MAX_STEPS; s++) {
        float still = (hp < 1.0f) ? 1.0f : 0.0f;
        float nh = ((hp + p * still) > THRESHOLD) ? still : 0.0f;
        hp = hp + p * still;
        rem = rem + nh * (1.0f - hp);
        hp = hp + nh * rem;
        float w = p * still + nh * rem;
        c = (1.0f - w) * c + w;              // x -> 1 in factor space
        nup = nup + still;
    }

    float4* __restrict__ o4 = reinterpret_cast<float4*>(out_state + base);
    #pragma unroll
    for (int i = 0; i < 4; i++) {
        float4 ov;
        ov.x = c * xv[i].x; ov.y = c * xv[i].y;
        ov.z = c * xv[i].z; ov.w = c * xv[i].w;
        o4[i * 64 + half * 32 + lane] = ov;
    }

    if (half == 0 && lane == 0 && out_ponder != nullptr)
        out_ponder[row] = nup + rem;
}

extern "C" void kernel_launch(void* const* d_in, const int* in_sizes, int n_in,
                              void* d_out, int out_size) {
    const float* x = (const float*)d_in[0];
    const float* W = (const float*)d_in[1];
    const float* b = (const float*)d_in[2];
    float* out = (float*)d_out;

    const int d = in_sizes[1];           // 1024
    const int n_rows = in_sizes[0] / d;  // B*S = 32768
    (void)n_in;

    float* out_ponder = nullptr;
    if ((long long)out_size >= (long long)n_rows * d + n_rows)
        out_ponder = out + (size_t)n_rows * d;

    const int blocks = (n_rows + ROWS_PER_BLOCK - 1) / ROWS_PER_BLOCK;
    act_kernel<<<blocks, THREADS>>>(x, W, b, out, out_ponder, n_rows);
}

// round 6
// speedup vs baseline: 1.0114x; 1.0114x over previous
#include <cuda_runtime.h>
#include <math.h>

// ACT collapses to a per-row scalar recursion:
//   p = sigmoid(x_row . W + b)           (scalar per row)
//   state = c * x_row,  c follows the same update with x -> 1
//   ponder = nup + rem
// Two warps per row (64 lanes, 4 float4 each): low register footprint ->
// full occupancy, while keeping MLP=4 independent LDG.128 per thread.
// All lanes redundantly run the exact fp32 scalar recursion.

#define D 1024
#define THREADS 256          // 8 warps -> 4 rows per block (2 warps/row)
#define ROWS_PER_BLOCK 4
#define MAX_STEPS 20
#define THRESHOLD 0.99f

__global__ __launch_bounds__(THREADS, 8) void act_kernel(
    const float* __restrict__ x,
    const float* __restrict__ W,
    const float* __restrict__ bvec,
    float* __restrict__ out_state,
    float* __restrict__ out_ponder,   // may be null
    int n_rows)
{
    __shared__ float warp_part[THREADS / 32];

    const int lane = threadIdx.x & 31;
    const int warp = threadIdx.x >> 5;
    const int half = warp & 1;                      // which half of the row
    const int row  = blockIdx.x * ROWS_PER_BLOCK + (warp >> 1);

    const bool active = (row < n_rows);
    const size_t base = (size_t)row * D;
    const float4* __restrict__ x4 = reinterpret_cast<const float4*>(x + base);
    const float4* __restrict__ w4 = reinterpret_cast<const float4*>(W);

    // Each lane: 4 independent LDG.128 (64 lanes x 4 x 4 floats = 1024 = D).
    // Coalesced: (i, half) selects a contiguous 32-float4 segment.
    float4 xv[4];
    float dot = 0.0f;
    if (active) {
        #pragma unroll
        for (int i = 0; i < 4; i++)
            xv[i] = x4[i * 64 + half * 32 + lane];
        #pragma unroll
        for (int i = 0; i < 4; i++) {
            const float4 wv = __ldg(&w4[i * 64 + half * 32 + lane]);
            dot += xv[i].x * wv.x + xv[i].y * wv.y
                 + xv[i].z * wv.z + xv[i].w * wv.w;
        }
    }

    // Warp-level reduce of this half-row.
    #pragma unroll
    for (int o = 16; o > 0; o >>= 1)
        dot += __shfl_xor_sync(0xffffffffu, dot, o);
    if (lane == 0) warp_part[warp] = dot;
    __syncthreads();

    if (!active) return;

    // Combine the two half-row partials (deterministic order: even + odd).
    const float z = warp_part[warp & ~1] + warp_part[warp | 1] + bvec[0];
    const float p = 1.0f / (1.0f + expf(-z));

    // Exact replication of the reference scan in scalar fp32 (all lanes).
    float hp = 0.0f, rem = 0.0f, nup = 0.0f, c = 0.0f;
    #pragma unroll
    for (int s = 0; s < MAX_STEPS; s++) {
        float still = (hp < 1.0f) ? 1.0f : 0.0f;
        float nh = ((hp + p * still) > THRESHOLD) ? still : 0.0f;
        hp = hp + p * still;
        rem = rem + nh * (1.0f - hp);
        hp = hp + nh * rem;
        float w = p * still + nh * rem;
        c = (1.0f - w) * c + w;              // x -> 1 in factor space
        nup = nup + still;
    }

    float4* __restrict__ o4 = reinterpret_cast<float4*>(out_state + base);
    #pragma unroll
    for (int i = 0; i < 4; i++) {
        float4 ov;
        ov.x = c * xv[i].x; ov.y = c * xv[i].y;
        ov.z = c * xv[i].z; ov.w = c * xv[i].w;
        o4[i * 64 + half * 32 + lane] = ov;
    }

    if (half == 0 && lane == 0 && out_ponder != nullptr)
        out_ponder[row] = nup + rem;
}

extern "C" void kernel_launch(void* const* d_in, const int* in_sizes, int n_in,
                              void* d_out, int out_size) {
    const float* x = (const float*)d_in[0];
    const float* W = (const float*)d_in[1];
    const float* b = (const float*)d_in[2];
    float* out = (float*)d_out;

    const int d = in_sizes[1];           // 1024
    const int n_rows = in_sizes[0] / d;  // B*S = 32768
    (void)n_in;

    float* out_ponder = nullptr;
    if ((long long)out_size >= (long long)n_rows * d + n_rows)
        out_ponder = out + (size_t)n_rows * d;

    const int blocks = (n_rows + ROWS_PER_BLOCK - 1) / ROWS_PER_BLOCK;
    act_kernel<<<blocks, THREADS>>>(x, W, b, out, out_ponder, n_rows);
}

// round 7
// speedup vs baseline: 1.0700x; 1.0580x over previous
#include <cuda_runtime.h>
#include <math.h>

// ACT collapses to a per-row scalar recursion:
//   p = sigmoid(x_row . W + b)           (scalar per row)
//   state = c * x_row,  c follows the same update with x -> 1
//   ponder = nup + rem
// Two warps per row (64 lanes, 4 float4 each), full occupancy, MLP=4.
// All lanes redundantly run the fp32 scalar recursion with a warp-uniform
// early exit: once hp >= 1, every further reference step is an exact no-op.

#define D 1024
#define THREADS 256          // 8 warps -> 4 rows per block (2 warps/row)
#define ROWS_PER_BLOCK 4
#define MAX_STEPS 20
#define THRESHOLD 0.99f

__global__ __launch_bounds__(THREADS, 8) void act_kernel(
    const float* __restrict__ x,
    const float* __restrict__ W,
    const float* __restrict__ bvec,
    float* __restrict__ out_state,
    float* __restrict__ out_ponder,   // may be null
    int n_rows)
{
    __shared__ float warp_part[THREADS / 32];

    const int lane = threadIdx.x & 31;
    const int warp = threadIdx.x >> 5;
    const int half = warp & 1;                      // which half of the row
    const int row  = blockIdx.x * ROWS_PER_BLOCK + (warp >> 1);

    const bool active = (row < n_rows);
    const size_t base = (size_t)row * D;
    const float4* __restrict__ x4 = reinterpret_cast<const float4*>(x + base);
    const float4* __restrict__ w4 = reinterpret_cast<const float4*>(W);

    // Each lane: 4 independent LDG.128 (64 lanes x 4 x 4 floats = 1024 = D).
    // x is read once and never reused -> streaming load (evict-first).
    float4 xv[4];
    float dot = 0.0f;
    if (active) {
        #pragma unroll
        for (int i = 0; i < 4; i++)
            xv[i] = __ldcs(&x4[i * 64 + half * 32 + lane]);
        #pragma unroll
        for (int i = 0; i < 4; i++) {
            const float4 wv = __ldg(&w4[i * 64 + half * 32 + lane]);
            dot += xv[i].x * wv.x + xv[i].y * wv.y
                 + xv[i].z * wv.z + xv[i].w * wv.w;
        }
    }

    // Warp-level reduce of this half-row.
    #pragma unroll
    for (int o = 16; o > 0; o >>= 1)
        dot += __shfl_xor_sync(0xffffffffu, dot, o);
    if (lane == 0) warp_part[warp] = dot;
    __syncthreads();

    if (!active) return;

    // Combine the two half-row partials (deterministic order: even + odd).
    const float z = warp_part[warp & ~1] + warp_part[warp | 1] + bvec[0];
    const float p = 1.0f / (1.0f + expf(-z));

    // Exact replication of the reference scan in scalar fp32. All lanes of a
    // warp hold identical values -> the early exit is warp-uniform. After
    // hp >= 1, the reference step is an exact no-op (still = 0), so breaking
    // is bit-identical to running the remaining steps.
    float hp = 0.0f, rem = 0.0f, nup = 0.0f, c = 0.0f;
    for (int s = 0; s < MAX_STEPS; s++) {
        if (hp >= 1.0f) break;                   // still == 0 -> exact no-op
        float still = 1.0f;                      // hp < 1 here
        float nh = ((hp + p) > THRESHOLD) ? still : 0.0f;
        hp = hp + p;
        rem = rem + nh * (1.0f - hp);
        hp = hp + nh * rem;
        float w = p + nh * rem - p * (1.0f - still); // still==1: w = p + nh*rem
        w = p * still + nh * rem;                    // keep reference op order
        c = (1.0f - w) * c + w;                  // x -> 1 in factor space
        nup = nup + still;
    }

    float4* __restrict__ o4 = reinterpret_cast<float4*>(out_state + base);
    #pragma unroll
    for (int i = 0; i < 4; i++) {
        float4 ov;
        ov.x = c * xv[i].x; ov.y = c * xv[i].y;
        ov.z = c * xv[i].z; ov.w = c * xv[i].w;
        __stcs(&o4[i * 64 + half * 32 + lane], ov);
    }

    if (half == 0 && lane == 0 && out_ponder != nullptr)
        out_ponder[row] = nup + rem;
}

extern "C" void kernel_launch(void* const* d_in, const int* in_sizes, int n_in,
                              void* d_out, int out_size) {
    const float* x = (const float*)d_in[0];
    const float* W = (const float*)d_in[1];
    const float* b = (const float*)d_in[2];
    float* out = (float*)d_out;

    const int d = in_sizes[1];           // 1024
    const int n_rows = in_sizes[0] / d;  // B*S = 32768
    (void)n_in;

    float* out_ponder = nullptr;
    if ((long long)out_size >= (long long)n_rows * d + n_rows)
        out_ponder = out + (size_t)n_rows * d;

    const int blocks = (n_rows + ROWS_PER_BLOCK - 1) / ROWS_PER_BLOCK;
    act_kernel<<<blocks, THREADS>>>(x, W, b, out, out_ponder, n_rows);
}